// round 5
// baseline (speedup 1.0000x reference)
#include <cuda_runtime.h>
#include <cstdint>

// Dims: Nt=64, Nr=64, Mt=32, Mr=32, G^2=4096, num_sc=32, B=64, R=8, N_r_RF=4
#define G2 4096
typedef unsigned long long u64;

// ---- device globals (no allocation allowed) ----
// Tables in (x, x, y, y) form (scaled by 1/8). Signs are applied in epilogues.
__device__ float4 g_W4[2048];                       // [d*32+m]
__device__ float4 g_F4[2048];                       // [c*32+a]
__device__ float2 g_S [(size_t)2048 * 4096];        // S[c*32+bp][g], 64 MB
__device__ float2 g_G1[(size_t)2048 * 2048];        // G1[b*32+m][c*32+s], 32 MB

// ---- f32x2 packed helpers ----
__device__ __forceinline__ u64 ffma2(u64 a, u64 b, u64 c) {
    u64 d; asm("fma.rn.f32x2 %0,%1,%2,%3;" : "=l"(d) : "l"(a), "l"(b), "l"(c)); return d;
}
__device__ __forceinline__ u64 fadd2(u64 a, u64 b) {
    u64 d; asm("add.rn.f32x2 %0,%1,%2;" : "=l"(d) : "l"(a), "l"(b)); return d;
}
__device__ __forceinline__ u64 pack2(float lo, float hi) {
    u64 r; asm("mov.b64 %0,{%1,%2};" : "=l"(r) : "f"(lo), "f"(hi)); return r;
}
__device__ __forceinline__ void unpack2(float& lo, float& hi, u64 v) {
    asm("mov.b64 {%0,%1},%2;" : "=f"(lo), "=f"(hi) : "l"(v));
}
// conj-form: out = A + (B.y, -B.x)
__device__ __forceinline__ u64 comb_conj(u64 A, u64 B) {
    float bl, bh; unpack2(bl, bh, B);
    return fadd2(A, pack2(bh, -bl));
}
// mul-form: out = A + (-B.y, B.x)
__device__ __forceinline__ u64 comb_mul(u64 A, u64 B) {
    float bl, bh; unpack2(bl, bh, B);
    return fadd2(A, pack2(-bh, bl));
}
__device__ __forceinline__ uint32_t saddr(const void* p) {
    return (uint32_t)__cvta_generic_to_shared(p);
}
__device__ __forceinline__ void lds_v2(u64& a, u64& b, uint32_t addr) {
    asm volatile("ld.shared.v2.b64 {%0,%1},[%2];" : "=l"(a), "=l"(b) : "r"(addr));
}
__device__ __forceinline__ void ldg_v2(u64& a, u64& b, const void* p) {
    asm("ld.global.nc.v2.b64 {%0,%1},[%2];" : "=l"(a), "=l"(b) : "l"(p));
}
__device__ __forceinline__ void ldg_v2_c(u64& a, u64& b, const void* p) {
    asm volatile("ld.global.v2.b64 {%0,%1},[%2];" : "=l"(a), "=l"(b) : "l"(p));
}
__device__ __forceinline__ void stg_v2(void* p, u64 a, u64 b) {
    asm volatile("st.global.v2.b64 [%0],{%1,%2};" :: "l"(p), "l"(a), "l"(b));
}
__device__ __forceinline__ void ldg4(u64* k, const float2* p) {
    ldg_v2(k[0], k[1], p);
    ldg_v2(k[2], k[3], p + 2);
}

// ---- setup: (x,x,y,y) tables ----
__global__ void setup_kernel(const float* __restrict__ kW, const float* __restrict__ kF) {
    int i = blockIdx.x * blockDim.x + threadIdx.x;
    if (i < 2048) {
        float s, c;
        sincosf(kW[i], &s, &c);
        g_W4[i] = make_float4(c * 0.125f, c * 0.125f, s * 0.125f, s * 0.125f);
        sincosf(kF[i], &s, &c);
        g_F4[i] = make_float4(c * 0.125f, c * 0.125f, s * 0.125f, s * 0.125f);
    }
}

// =====================================================================
// Shared GEMM-shaped core: thread tile = 4 rows x 4 cols, reduce over 64.
// Per step: 4 LDS.v2 + 2 LDG.v2 + 32 FFMA2.
//   accA/accB: [row i][col q] -> index i*4+q
// =====================================================================
#define CORE_LOOP(PTR, STRIDE, WADDR)                                        \
    u64 accA[16], accB[16];                                                  \
    _Pragma("unroll")                                                        \
    for (int i = 0; i < 16; ++i) { accA[i] = 0ull; accB[i] = 0ull; }         \
    u64 ka[4], kb[4];                                                        \
    ldg4(ka, PTR);                                                           \
    ldg4(kb, PTR + (STRIDE));                                                \
    _Pragma("unroll 2")                                                      \
    for (int dd = 0; dd < 64; ++dd) {                                        \
        u64 kn[4] = {0ull, 0ull, 0ull, 0ull};                                \
        if (dd + 2 < 64) ldg4(kn, PTR + (size_t)(dd + 2) * (STRIDE));        \
        _Pragma("unroll")                                                    \
        for (int i = 0; i < 4; ++i) {                                        \
            u64 wxx, wyy;                                                    \
            lds_v2(wxx, wyy, (WADDR) + (uint32_t)dd * 512 + i * 16);         \
            _Pragma("unroll")                                                \
            for (int q = 0; q < 4; ++q) {                                    \
                accA[i * 4 + q] = ffma2(wxx, ka[q], accA[i * 4 + q]);        \
                accB[i * 4 + q] = ffma2(wyy, ka[q], accB[i * 4 + q]);        \
            }                                                                \
        }                                                                    \
        _Pragma("unroll")                                                    \
        for (int q = 0; q < 4; ++q) { ka[q] = kb[q]; kb[q] = kn[q]; }        \
    }

// =====================================================================
// passA: S[c*32+bp][g] = sum_d conj(W[d,bp]) * K[c*64+d][g]
// grid 2048 = (c=64, gtile=32); 256 thr; tile 4bp x 4g.
// =====================================================================
__global__ void __launch_bounds__(256) sA_kernel(const float2* __restrict__ K) {
    __shared__ float4 Wt[2048];
    const int t = threadIdx.x;
#pragma unroll
    for (int i = 0; i < 8; ++i) Wt[t + 256 * i] = g_W4[t + 256 * i];
    __syncthreads();

    const int c = blockIdx.x >> 5, gt = blockIdx.x & 31;
    const int gp = t & 31, bg = t >> 5;
    const int g = gt * 128 + gp * 4;

    const float2* Kp = K + (size_t)(c * 64) * G2 + g;
    const uint32_t waddr = saddr(Wt) + (uint32_t)(bg * 4) * 16;

    CORE_LOOP(Kp, G2, waddr)

#pragma unroll
    for (int i = 0; i < 4; ++i) {
        float2* Sp = g_S + (size_t)(c * 32 + bg * 4 + i) * G2 + g;
        stg_v2(Sp,     comb_conj(accA[i * 4],     accB[i * 4]),
                       comb_conj(accA[i * 4 + 1], accB[i * 4 + 1]));
        stg_v2(Sp + 2, comb_conj(accA[i * 4 + 2], accB[i * 4 + 2]),
                       comb_conj(accA[i * 4 + 3], accB[i * 4 + 3]));
    }
}

// =====================================================================
// passB: Phi[(a*32+bp)][g] = sum_c F[c,a] * S[c*32+bp][g]
// grid 1024 = (bp=32, gtile=32); tile 4a x 4g.
// =====================================================================
__global__ void __launch_bounds__(256) phiB_kernel(float2* __restrict__ Phi) {
    __shared__ float4 Ft[2048];
    const int t = threadIdx.x;
#pragma unroll
    for (int i = 0; i < 8; ++i) Ft[t + 256 * i] = g_F4[t + 256 * i];
    __syncthreads();

    const int bp = blockIdx.x >> 5, gt = blockIdx.x & 31;
    const int gp = t & 31, ag = t >> 5;
    const int g = gt * 128 + gp * 4;

    const float2* Sp = g_S + (size_t)bp * G2 + g;          // + c*32*G2
    const uint32_t faddr = saddr(Ft) + (uint32_t)(ag * 4) * 16;

    CORE_LOOP(Sp, (size_t)32 * G2, faddr)

#pragma unroll
    for (int i = 0; i < 4; ++i) {
        float2* Pp = Phi + (size_t)((ag * 4 + i) * 32 + bp) * G2 + g;
        stg_v2(Pp,     comb_mul(accA[i * 4],     accB[i * 4]),
                       comb_mul(accA[i * 4 + 1], accB[i * 4 + 1]));
        stg_v2(Pp + 2, comb_mul(accA[i * 4 + 2], accB[i * 4 + 2]),
                       comb_mul(accA[i * 4 + 3], accB[i * 4 + 3]));
    }
}

// =====================================================================
// y1: G1[b*32+m][cs] = sum_d conj(W[d,m]) * H[b][d][cs]
// grid 1024 = (b=64, cstile=16); tile 4m x 4cs.
// =====================================================================
__global__ void __launch_bounds__(256) y1_kernel(const float2* __restrict__ H) {
    __shared__ float4 Wt[2048];
    const int t = threadIdx.x;
#pragma unroll
    for (int i = 0; i < 8; ++i) Wt[t + 256 * i] = g_W4[t + 256 * i];
    __syncthreads();

    const int b = blockIdx.x >> 4, cst = blockIdx.x & 15;
    const int csp = t & 31, mg = t >> 5;
    const int cs = cst * 128 + csp * 4;

    const float2* Hp = H + (size_t)b * 131072 + cs;        // + d*2048
    const uint32_t waddr = saddr(Wt) + (uint32_t)(mg * 4) * 16;

    CORE_LOOP(Hp, 2048, waddr)

#pragma unroll
    for (int i = 0; i < 4; ++i) {
        float2* Gp = g_G1 + (size_t)(b * 32 + mg * 4 + i) * 2048 + cs;
        stg_v2(Gp,     comb_conj(accA[i * 4],     accB[i * 4]),
                       comb_conj(accA[i * 4 + 1], accB[i * 4 + 1]));
        stg_v2(Gp + 2, comb_conj(accA[i * 4 + 2], accB[i * 4 + 2]),
                       comb_conj(accA[i * 4 + 3], accB[i * 4 + 3]));
    }
}

// =====================================================================
// y2s: Y[b][(a*32+m)][s] = sum_c F[c,a] * G1[b*32+m][c*32+s]
// grid 512: 4 (b,m) per block; per (b,m) 64 thr: 8 s-quads x 8 a-groups;
// tile 4a x 4s.
// =====================================================================
__global__ void __launch_bounds__(256) y2s_kernel(float2* __restrict__ Y) {
    __shared__ float4 Ft[2048];
    const int t = threadIdx.x;
#pragma unroll
    for (int i = 0; i < 8; ++i) Ft[t + 256 * i] = g_F4[t + 256 * i];
    __syncthreads();

    const int bm = blockIdx.x * 4 + (t >> 6);
    const int b = bm >> 5, m = bm & 31;
    const int sp = t & 7, ag = (t >> 3) & 7;
    const int s = sp * 4;

    const float2* Gp = g_G1 + (size_t)bm * 2048 + s;       // + c*32
    const uint32_t faddr = saddr(Ft) + (uint32_t)(ag * 4) * 16;

    CORE_LOOP(Gp, 32, faddr)

#pragma unroll
    for (int i = 0; i < 4; ++i) {
        float2* yp = Y + (size_t)(b * 1024 + (ag * 4 + i) * 32 + m) * 32 + s;
        stg_v2(yp,     comb_mul(accA[i * 4],     accB[i * 4]),
                       comb_mul(accA[i * 4 + 1], accB[i * 4 + 1]));
        stg_v2(yp + 2, comb_mul(accA[i * 4 + 2], accB[i * 4 + 2]),
                       comb_mul(accA[i * 4 + 3], accB[i * 4 + 3]));
    }
}

// =====================================================================
// y2n: Y[b][a*32 + r*4 + j][s] += sum_n conj(W[n, r*4+j]) * noise[b,r,n,x]
// x = a*32+s; grid 512 = (b,r); thread owns x-quad (x0 = t*4) and 4 j.
// Pure 256 MB DRAM stream + RMW tail.
// =====================================================================
__global__ void __launch_bounds__(256) y2n_kernel(const float2* __restrict__ noise,
                                                  float2* __restrict__ Y) {
    __shared__ float4 Wn[256];   // [n*4+j] = (x,x,y,y)
    const int t = threadIdx.x;
    const int b = blockIdx.x >> 3, r = blockIdx.x & 7;
    Wn[t] = g_W4[(t >> 2) * 32 + r * 4 + (t & 3)];
    __syncthreads();

    const int x0 = t * 4;
    const uint32_t wn = saddr(Wn);
    const float2* np = noise + (size_t)(b * 8 + r) * 65536 + x0;

    u64 accA[16], accB[16];
#pragma unroll
    for (int i = 0; i < 16; ++i) { accA[i] = 0ull; accB[i] = 0ull; }

#pragma unroll 4
    for (int n = 0; n < 64; ++n) {
        u64 v[4];
        ldg4(v, np + (size_t)n * 1024);
#pragma unroll
        for (int j = 0; j < 4; ++j) {
            u64 wxx, wyy;
            lds_v2(wxx, wyy, wn + (uint32_t)((n * 4 + j) << 4));
#pragma unroll
            for (int q = 0; q < 4; ++q) {
                accA[j * 4 + q] = ffma2(wxx, v[q], accA[j * 4 + q]);
                accB[j * 4 + q] = ffma2(wyy, v[q], accB[j * 4 + q]);
            }
        }
    }

    const int a = x0 >> 5, s = x0 & 31;
#pragma unroll
    for (int j = 0; j < 4; ++j) {
        float2* yp = Y + (size_t)(b * 1024 + a * 32 + r * 4 + j) * 32 + s;
        u64 y0, y1, y2, y3;
        ldg_v2_c(y0, y1, yp);
        ldg_v2_c(y2, y3, yp + 2);
        stg_v2(yp,     fadd2(y0, comb_conj(accA[j * 4],     accB[j * 4])),
                       fadd2(y1, comb_conj(accA[j * 4 + 1], accB[j * 4 + 1])));
        stg_v2(yp + 2, fadd2(y2, comb_conj(accA[j * 4 + 2], accB[j * 4 + 2])),
                       fadd2(y3, comb_conj(accA[j * 4 + 3], accB[j * 4 + 3])));
    }
}

extern "C" void kernel_launch(void* const* d_in, const int* in_sizes, int n_in,
                              void* d_out, int out_size) {
    const float2* H     = (const float2*)d_in[0];  // (64,64,64,32,2) f32
    const float2* noise = (const float2*)d_in[1];  // (64,8,64,1024,2) f32
    const float*  kW    = (const float*)d_in[2];   // (64,32)
    const float*  kF    = (const float*)d_in[3];   // (64,32)
    const float2* K     = (const float2*)d_in[4];  // (4096,4096,2)

    float2* Phi = (float2*)d_out;                   // 1024*4096 complex
    float2* Y   = Phi + (size_t)1024 * 4096;        // 64*1024*32 complex

    setup_kernel<<<8, 256>>>(kW, kF);
    sA_kernel  <<<2048, 256>>>(K);
    y1_kernel  <<<1024, 256>>>(H);
    phiB_kernel<<<1024, 256>>>(Phi);
    y2s_kernel <<<512, 256>>>(Y);
    y2n_kernel <<<512, 256>>>(noise, Y);
}